// round 7
// baseline (speedup 1.0000x reference)
#include <cuda_runtime.h>
#include <math.h>

#define M_   24
#define TS_  60
#define NX_  192
#define NY_  192
#define NG_  50
#define T_   50
#define HD_  32   // H*D
#define H_   4
#define D_   8

// jnp.linspace(0,100,192): delta = 100/191 (f32), endpoint forced exact.
__device__ __forceinline__ float gridx(int k) {
    return (k == NX_ - 1) ? 100.0f : (float)k * (100.0f / 191.0f);
}

__global__ __launch_bounds__(256)
void fused_kernel(const float* __restrict__ c1,
                  const float* __restrict__ c2,
                  const float* __restrict__ params,
                  const float* __restrict__ src_y,
                  const float* __restrict__ stl,
                  const float* __restrict__ Wq,
                  const float* __restrict__ bq,
                  const float* __restrict__ Wk,
                  const float* __restrict__ bk,
                  const float* __restrict__ lyt_p,
                  const float* __restrict__ cut_p,
                  const float* __restrict__ nit_p,
                  float* __restrict__ out)
{
    // ---- per-block table shared memory (~38.6 KB static) ----
    __shared__ float s_y[M_][NY_];          // 18.4 KB, staged src_y
    __shared__ int   s_off[T_][M_];         // 4.8 KB  slice offsets
    __shared__ int   s_iy[M_][NG_];         // 4.8 KB
    __shared__ float s_e0[M_][NG_];         // 4.8 KB  w*my*(1-fy)
    __shared__ float s_e1[M_][NG_];         // 4.8 KB  w*my*fy
    __shared__ int   s_ix[NG_];
    __shared__ float s_fx[NG_];
    __shared__ float s_mx[NG_];
    __shared__ float s_Wq[3*HD_], s_Wk[3*HD_], s_bq[HD_], s_bk[HD_], s_Q[HD_];
    __shared__ float s_ly[M_], s_cu[M_], s_ni[M_], s_scale[M_], s_stl[M_];
    __shared__ float s_logits[M_][H_];
    __shared__ float s_sm[H_][M_];
    __shared__ float s_swv[M_], s_wa[M_], s_w[M_];
    __shared__ float s_ssum, s_wsum;

    const int tid = threadIdx.x;
    const float lyt = __ldg(lyt_p);
    const float t_ly = (lyt - 30.0f) / 90.0f;
    const float t_cu = __ldg(cut_p) / 0.0029f;
    const float t_ni = __ldg(nit_p) / 0.0018f;

    // ---- stage small inputs (coalesced) ----
    for (int p = tid; p < M_ * NY_; p += blockDim.x)
        s_y[p / NY_][p % NY_] = __ldg(src_y + p);
    if (tid < 3 * HD_) { s_Wq[tid] = __ldg(Wq + tid); s_Wk[tid] = __ldg(Wk + tid); }
    if (tid < HD_)     { s_bq[tid] = __ldg(bq + tid); s_bk[tid] = __ldg(bk + tid); }
    if (tid < M_) {
        float lys = __ldg(params + 3*tid + 0);
        s_ly[tid] = (lys - 30.0f) / 90.0f;
        s_cu[tid] = __ldg(params + 3*tid + 1) / 0.0029f;
        s_ni[tid] = __ldg(params + 3*tid + 2) / 0.0018f;
        s_scale[tid] = lyt / lys;
        s_stl[tid] = __ldg(stl + tid);
    }
    __syncthreads();

    // ---- Q vector ----
    if (tid < HD_)
        s_Q[tid] = t_ly*s_Wq[tid] + t_cu*s_Wq[HD_+tid] + t_ni*s_Wq[2*HD_+tid] + s_bq[tid];
    __syncthreads();

    // ---- logits: one thread per (m,h) ----
    if (tid < M_ * H_) {
        int m = tid / H_, h = tid % H_;
        float acc = 0.0f;
        for (int d = 0; d < D_; d++) {
            int k = h*D_ + d;
            float Kv = s_ly[m]*s_Wk[k] + s_cu[m]*s_Wk[HD_+k] + s_ni[m]*s_Wk[2*HD_+k] + s_bk[k];
            acc += Kv * s_Q[k];
        }
        s_logits[m][h] = acc * (1.0f / sqrtf((float)D_));
    }
    __syncthreads();

    // ---- softmax over m, per head ----
    if (tid < H_) {
        int h = tid;
        float mx = -1e30f;
        for (int m = 0; m < M_; m++) mx = fmaxf(mx, s_logits[m][h]);
        float s = 0.0f;
        for (int m = 0; m < M_; m++) s += expf(s_logits[m][h] - mx);
        for (int m = 0; m < M_; m++) s_sm[h][m] = expf(s_logits[m][h] - mx) / s;
    }
    // ---- Gaussian similarity (parallel over m) ----
    if (tid < M_) {
        float d2 = ((s_ly[tid]-t_ly)*(s_ly[tid]-t_ly) +
                    (s_cu[tid]-t_cu)*(s_cu[tid]-t_cu) +
                    (s_ni[tid]-t_ni)*(s_ni[tid]-t_ni)) / (0.2f*0.2f);
        s_swv[tid] = expf(-d2 * 0.5f);
    }
    __syncthreads();
    if (tid == 0) {
        float s = 0.0f;
        for (int m = 0; m < M_; m++) s += s_swv[m];
        s_ssum = s;
    }
    __syncthreads();
    if (tid < M_) {
        float attn = (s_sm[0][tid] + s_sm[1][tid] + s_sm[2][tid] + s_sm[3][tid]) * 0.25f;
        s_wa[tid] = attn * (s_swv[tid] / (s_ssum + 1e-12f));
    }
    __syncthreads();
    if (tid == 0) {
        float s = 0.0f;
        for (int m = 0; m < M_; m++) s += s_wa[m];
        s_wsum = s;
    }
    __syncthreads();
    if (tid < M_)
        s_w[tid] = s_wa[tid] / (s_wsum + 1e-12f);

    // ---- x-axis interp setup ----
    if (tid < NG_) {
        float q = (tid == NG_-1) ? 100.0f : (float)tid * (100.0f / 49.0f);
        int lo = 0, hi = NX_;
        while (lo < hi) { int mid = (lo + hi) >> 1; if (gridx(mid) <= q) lo = mid + 1; else hi = mid; }
        int idx = min(max(lo - 1, 0), NX_ - 2);
        float g0 = gridx(idx), g1 = gridx(idx + 1);
        s_ix[tid] = idx;
        s_fx[tid] = (q - g0) / (g1 - g0);
        s_mx[tid] = (q >= 0.0f && q <= 100.0f) ? 1.0f : 0.0f;
    }

    // ---- time index -> slice offsets (round-half-even) ----
    for (int p = tid; p < T_ * M_; p += blockDim.x) {
        int t = p / M_, m = p % M_;
        float tv = (t == T_-1) ? 200.0f : (float)t * (200.0f / 49.0f);
        float r = rintf(tv / s_stl[m] * (float)(TS_ - 1));
        int ti = min(max((int)r, 0), TS_ - 1);
        s_off[t][m] = (m * TS_ + ti) * (NX_ * NY_);
    }
    __syncthreads();   // s_w, s_y ready before y-table loop (uses s_w)

    // ---- y-axis tables per (m,j): binary search in SHARED ----
    for (int p = tid; p < M_ * NG_; p += blockDim.x) {
        int m = p / NG_, j = p % NG_;
        float q  = (float)j / 49.0f * lyt;
        float sc = s_scale[m];
        const float* ys = s_y[m];
        int lo = 0, hi = NY_;
        while (lo < hi) { int mid = (lo + hi) >> 1; if (ys[mid]*sc <= q) lo = mid + 1; else hi = mid; }
        int idx = min(max(lo - 1, 0), NY_ - 2);
        float gy0 = ys[idx] * sc, gy1 = ys[idx + 1] * sc;
        float fy = (q - gy0) / (gy1 - gy0);
        float inb = (q >= ys[0]*sc && q <= ys[NY_-1]*sc) ? 1.0f : 0.0f;
        float wm = s_w[m] * inb;
        s_iy[m][j] = idx;
        s_e0[m][j] = wm * (1.0f - fy);
        s_e1[m][j] = wm * fy;
    }
    __syncthreads();

    // ---- main gather: 2 outputs per thread (t and t+25; same f,i,j) ----
    const int gidx = blockIdx.x * blockDim.x + tid;
    const int nthreads = 2 * (T_/2) * NG_ * NG_;   // 125000: f x t0 x i x j
    if (gidx >= nthreads) return;

    const int j  = gidx % NG_;
    const int i  = (gidx / NG_) % NG_;
    const int t0 = (gidx / (NG_ * NG_)) % (T_/2);
    const int f  = gidx / ((T_/2) * NG_ * NG_);    // 0 or 1
    const int t1 = t0 + T_/2;

    const float* __restrict__ base = f ? c2 : c1;
    const int   ixN = s_ix[i] * NY_;
    const float fx  = s_fx[i];
    const float fx1 = 1.0f - fx;

    float acc0 = 0.0f, acc1 = 0.0f;
#pragma unroll 4
    for (int m = 0; m < M_; m++) {
        const int   iy = s_iy[m][j];
        const float e0 = s_e0[m][j];
        const float e1 = s_e1[m][j];
        const float* __restrict__ p0 = base + s_off[t0][m] + ixN + iy;
        const float* __restrict__ p1 = base + s_off[t1][m] + ixN + iy;
        float a00 = __ldg(p0);
        float a01 = __ldg(p0 + 1);
        float a10 = __ldg(p0 + NY_);
        float a11 = __ldg(p0 + NY_ + 1);
        float b00 = __ldg(p1);
        float b01 = __ldg(p1 + 1);
        float b10 = __ldg(p1 + NY_);
        float b11 = __ldg(p1 + NY_ + 1);
        acc0 += (a00 * fx1 + a10 * fx) * e0 + (a01 * fx1 + a11 * fx) * e1;
        acc1 += (b00 * fx1 + b10 * fx) * e0 + (b01 * fx1 + b11 * fx) * e1;
    }
    float v0 = acc0 * s_mx[i];
    float v1 = acc1 * s_mx[i];
    if (f == 0 && j == 0)       { float c = __ldg(cut_p); v0 = c; v1 = c; }
    if (f == 1 && j == NG_ - 1) { float c = __ldg(nit_p); v0 = c; v1 = c; }

    out[((f * T_ + t0) * NG_ + i) * NG_ + j] = v0;
    out[((f * T_ + t1) * NG_ + i) * NG_ + j] = v1;
}

extern "C" void kernel_launch(void* const* d_in, const int* in_sizes, int n_in,
                              void* d_out, int out_size)
{
    const float* c1    = (const float*)d_in[0];
    const float* c2    = (const float*)d_in[1];
    const float* params= (const float*)d_in[2];
    const float* src_y = (const float*)d_in[3];
    const float* stl   = (const float*)d_in[4];
    const float* Wq    = (const float*)d_in[5];
    const float* bq    = (const float*)d_in[6];
    const float* Wk    = (const float*)d_in[7];
    const float* bk    = (const float*)d_in[8];
    const float* lyt   = (const float*)d_in[9];
    const float* cut   = (const float*)d_in[10];
    const float* nit   = (const float*)d_in[11];
    float* out = (float*)d_out;

    const int threads = 2 * (T_/2) * NG_ * NG_;   // 125000
    fused_kernel<<<(threads + 255) / 256, 256>>>(
        c1, c2, params, src_y, stl, Wq, bq, Wk, bk, lyt, cut, nit, out);
}

// round 8
// speedup vs baseline: 1.5000x; 1.5000x over previous
#include <cuda_runtime.h>
#include <math.h>

#define M_   24
#define TS_  60
#define NX_  192
#define NY_  192
#define NG_  50
#define T_   50
#define HD_  32   // H*D
#define H_   4
#define D_   8
#define BLK_ 512

// jnp.linspace(0,100,192): delta = 100/191 (f32), endpoint forced exact.
__device__ __forceinline__ float gridx(int k) {
    return (k == NX_ - 1) ? 100.0f : (float)k * (100.0f / 191.0f);
}

__global__ __launch_bounds__(BLK_)
void fused_kernel(const float* __restrict__ c1,
                  const float* __restrict__ c2,
                  const float* __restrict__ params,
                  const float* __restrict__ src_y,
                  const float* __restrict__ stl,
                  const float* __restrict__ Wq,
                  const float* __restrict__ bq,
                  const float* __restrict__ Wk,
                  const float* __restrict__ bk,
                  const float* __restrict__ lyt_p,
                  const float* __restrict__ cut_p,
                  const float* __restrict__ nit_p,
                  float* __restrict__ out)
{
    // ---- shared: ~34.9 KB -> 4 blocks x 512 thr = 64 warps/SM ----
    __shared__ float s_y[M_][NY_];           // 18.4 KB (setup scratch)
    __shared__ float s_e0[M_][NG_];          // 4.8 KB  w*my*(1-fy)
    __shared__ float s_e1[M_][NG_];          // 4.8 KB  w*my*fy
    __shared__ short s_iy[M_][NG_];          // 2.4 KB
    __shared__ unsigned char s_ti[T_][M_];   // 1.2 KB  time slice index
    __shared__ int   s_ix[NG_];
    __shared__ float s_fx[NG_];
    __shared__ float s_mx[NG_];
    __shared__ float s_Wq[3*HD_], s_Wk[3*HD_], s_bq[HD_], s_bk[HD_], s_Q[HD_];
    __shared__ float s_ly[M_], s_cu[M_], s_ni[M_], s_scale[M_], s_stl[M_];
    __shared__ float s_logits[M_][H_];
    __shared__ float s_sm[H_][M_];
    __shared__ float s_swv[M_], s_wa[M_], s_w[M_];
    __shared__ float s_ssum, s_wsum;

    const int tid = threadIdx.x;
    const float lyt = __ldg(lyt_p);
    const float t_ly = (lyt - 30.0f) / 90.0f;
    const float t_cu = __ldg(cut_p) / 0.0029f;
    const float t_ni = __ldg(nit_p) / 0.0018f;

    // ---- stage small inputs (coalesced) ----
    for (int p = tid; p < M_ * NY_; p += BLK_)
        s_y[p / NY_][p % NY_] = __ldg(src_y + p);
    if (tid < 3 * HD_) { s_Wq[tid] = __ldg(Wq + tid); s_Wk[tid] = __ldg(Wk + tid); }
    if (tid < HD_)     { s_bq[tid] = __ldg(bq + tid); s_bk[tid] = __ldg(bk + tid); }
    if (tid < M_) {
        float lys = __ldg(params + 3*tid + 0);
        s_ly[tid] = (lys - 30.0f) / 90.0f;
        s_cu[tid] = __ldg(params + 3*tid + 1) / 0.0029f;
        s_ni[tid] = __ldg(params + 3*tid + 2) / 0.0018f;
        s_scale[tid] = lyt / lys;
        s_stl[tid] = __ldg(stl + tid);
    }
    __syncthreads();

    // ---- Q vector ----
    if (tid < HD_)
        s_Q[tid] = t_ly*s_Wq[tid] + t_cu*s_Wq[HD_+tid] + t_ni*s_Wq[2*HD_+tid] + s_bq[tid];
    __syncthreads();

    // ---- logits: one thread per (m,h) ----
    if (tid < M_ * H_) {
        int m = tid / H_, h = tid % H_;
        float acc = 0.0f;
        for (int d = 0; d < D_; d++) {
            int k = h*D_ + d;
            float Kv = s_ly[m]*s_Wk[k] + s_cu[m]*s_Wk[HD_+k] + s_ni[m]*s_Wk[2*HD_+k] + s_bk[k];
            acc += Kv * s_Q[k];
        }
        s_logits[m][h] = acc * (1.0f / sqrtf((float)D_));
    }
    __syncthreads();

    // ---- softmax over m, per head ----
    if (tid < H_) {
        int h = tid;
        float mx = -1e30f;
        for (int m = 0; m < M_; m++) mx = fmaxf(mx, s_logits[m][h]);
        float s = 0.0f;
        for (int m = 0; m < M_; m++) s += expf(s_logits[m][h] - mx);
        for (int m = 0; m < M_; m++) s_sm[h][m] = expf(s_logits[m][h] - mx) / s;
    }
    // ---- Gaussian similarity ----
    if (tid < M_) {
        float d2 = ((s_ly[tid]-t_ly)*(s_ly[tid]-t_ly) +
                    (s_cu[tid]-t_cu)*(s_cu[tid]-t_cu) +
                    (s_ni[tid]-t_ni)*(s_ni[tid]-t_ni)) / (0.2f*0.2f);
        s_swv[tid] = expf(-d2 * 0.5f);
    }
    __syncthreads();
    if (tid == 0) {
        float s = 0.0f;
        for (int m = 0; m < M_; m++) s += s_swv[m];
        s_ssum = s;
    }
    __syncthreads();
    if (tid < M_) {
        float attn = (s_sm[0][tid] + s_sm[1][tid] + s_sm[2][tid] + s_sm[3][tid]) * 0.25f;
        s_wa[tid] = attn * (s_swv[tid] / (s_ssum + 1e-12f));
    }
    __syncthreads();
    if (tid == 0) {
        float s = 0.0f;
        for (int m = 0; m < M_; m++) s += s_wa[m];
        s_wsum = s;
    }
    __syncthreads();
    if (tid < M_)
        s_w[tid] = s_wa[tid] / (s_wsum + 1e-12f);

    // ---- x-axis interp setup ----
    if (tid < NG_) {
        float q = (tid == NG_-1) ? 100.0f : (float)tid * (100.0f / 49.0f);
        int lo = 0, hi = NX_;
        while (lo < hi) { int mid = (lo + hi) >> 1; if (gridx(mid) <= q) lo = mid + 1; else hi = mid; }
        int idx = min(max(lo - 1, 0), NX_ - 2);
        float g0 = gridx(idx), g1 = gridx(idx + 1);
        s_ix[tid] = idx;
        s_fx[tid] = (q - g0) / (g1 - g0);
        s_mx[tid] = (q >= 0.0f && q <= 100.0f) ? 1.0f : 0.0f;
    }

    // ---- time slice index (round-half-even) ----
    for (int p = tid; p < T_ * M_; p += BLK_) {
        int t = p / M_, m = p % M_;
        float tv = (t == T_-1) ? 200.0f : (float)t * (200.0f / 49.0f);
        float r = rintf(tv / s_stl[m] * (float)(TS_ - 1));
        s_ti[t][m] = (unsigned char)min(max((int)r, 0), TS_ - 1);
    }
    __syncthreads();   // s_w + s_y ready

    // ---- y-axis tables per (m,j): binary search in SHARED ----
    for (int p = tid; p < M_ * NG_; p += BLK_) {
        int m = p / NG_, j = p % NG_;
        float q  = (float)j / 49.0f * lyt;
        float sc = s_scale[m];
        const float* ys = s_y[m];
        int lo = 0, hi = NY_;
        while (lo < hi) { int mid = (lo + hi) >> 1; if (ys[mid]*sc <= q) lo = mid + 1; else hi = mid; }
        int idx = min(max(lo - 1, 0), NY_ - 2);
        float gy0 = ys[idx] * sc, gy1 = ys[idx + 1] * sc;
        float fy = (q - gy0) / (gy1 - gy0);
        float inb = (q >= ys[0]*sc && q <= ys[NY_-1]*sc) ? 1.0f : 0.0f;
        float wm = s_w[m] * inb;
        s_iy[m][j] = (short)idx;
        s_e0[m][j] = wm * (1.0f - fy);
        s_e1[m][j] = wm * fy;
    }
    __syncthreads();

    // ---- main gather: 2 outputs per thread (t0 and t0+25; same f,i,j) ----
    const int gidx = blockIdx.x * BLK_ + tid;
    const int nthreads = 2 * (T_/2) * NG_ * NG_;   // 125000
    if (gidx >= nthreads) return;

    const int j  = gidx % NG_;
    const int i  = (gidx / NG_) % NG_;
    const int t0 = (gidx / (NG_ * NG_)) % (T_/2);
    const int f  = gidx / ((T_/2) * NG_ * NG_);
    const int t1 = t0 + T_/2;

    const float* __restrict__ base = f ? c2 : c1;
    const int   ixN = s_ix[i] * NY_;
    const float fx  = s_fx[i];
    const float fx1 = 1.0f - fx;

    float acc0 = 0.0f, acc1 = 0.0f;
#pragma unroll 4
    for (int m = 0; m < M_; m++) {
        const int   iy = s_iy[m][j];
        const float e0 = s_e0[m][j];
        const float e1 = s_e1[m][j];
        const int base_m = m * TS_ * (NX_*NY_) + ixN + iy;
        const float* __restrict__ p0 = base + base_m + (int)s_ti[t0][m] * (NX_*NY_);
        const float* __restrict__ p1 = base + base_m + (int)s_ti[t1][m] * (NX_*NY_);
        float a00 = __ldg(p0);
        float a01 = __ldg(p0 + 1);
        float a10 = __ldg(p0 + NY_);
        float a11 = __ldg(p0 + NY_ + 1);
        float b00 = __ldg(p1);
        float b01 = __ldg(p1 + 1);
        float b10 = __ldg(p1 + NY_);
        float b11 = __ldg(p1 + NY_ + 1);
        acc0 += (a00 * fx1 + a10 * fx) * e0 + (a01 * fx1 + a11 * fx) * e1;
        acc1 += (b00 * fx1 + b10 * fx) * e0 + (b01 * fx1 + b11 * fx) * e1;
    }
    float v0 = acc0 * s_mx[i];
    float v1 = acc1 * s_mx[i];
    if (f == 0 && j == 0)       { float c = __ldg(cut_p); v0 = c; v1 = c; }
    if (f == 1 && j == NG_ - 1) { float c = __ldg(nit_p); v0 = c; v1 = c; }

    out[((f * T_ + t0) * NG_ + i) * NG_ + j] = v0;
    out[((f * T_ + t1) * NG_ + i) * NG_ + j] = v1;
}

extern "C" void kernel_launch(void* const* d_in, const int* in_sizes, int n_in,
                              void* d_out, int out_size)
{
    const float* c1    = (const float*)d_in[0];
    const float* c2    = (const float*)d_in[1];
    const float* params= (const float*)d_in[2];
    const float* src_y = (const float*)d_in[3];
    const float* stl   = (const float*)d_in[4];
    const float* Wq    = (const float*)d_in[5];
    const float* bq    = (const float*)d_in[6];
    const float* Wk    = (const float*)d_in[7];
    const float* bk    = (const float*)d_in[8];
    const float* lyt   = (const float*)d_in[9];
    const float* cut   = (const float*)d_in[10];
    const float* nit   = (const float*)d_in[11];
    float* out = (float*)d_out;

    const int threads = 2 * (T_/2) * NG_ * NG_;   // 125000
    fused_kernel<<<(threads + BLK_ - 1) / BLK_, BLK_>>>(
        c1, c2, params, src_y, stl, Wq, bq, Wk, bk, lyt, cut, nit, out);
}